// round 2
// baseline (speedup 1.0000x reference)
#include <cuda_runtime.h>
#include <math.h>

// Problem constants
#define T_LEN 2048
#define DIMX 2048
#define NH 16
#define NOPE 128
#define ROPE 64
#define VDIM 128
#define QKD 192          // NOPE + ROPE
#define Q_LORA 768
#define KV_LORA 512
#define KVA_OUT 576      // KV_LORA + ROPE
#define SOFTSCALE (-96.0f)   // QKD * -0.5 in the reference (multiplication!)
#define EPS 1e-6f

// -------------------- scratch (device globals; no allocs allowed) --------------------
__device__ float g_qa  [(size_t)T_LEN * Q_LORA];         // x @ wq_a^T, rmsnormed in place
__device__ float g_q   [(size_t)T_LEN * NH * QKD];       // q after wq_b
__device__ float g_kvf [(size_t)T_LEN * KVA_OUT];        // x @ wkv_a^T
__device__ float g_ckvn[(size_t)T_LEN * KV_LORA];        // rmsnorm(c_kv)
__device__ float g_kpe [(size_t)T_LEN * ROPE];           // rope(k_pe)
__device__ float g_kv  [(size_t)T_LEN * NH * (NOPE + VDIM)];
__device__ float g_qh  [(size_t)NH * T_LEN * QKD];       // per-head Q (nope|rope)
__device__ float g_kh  [(size_t)NH * T_LEN * QKD];       // per-head K (nope|rope)
__device__ float g_v   [(size_t)NH * T_LEN * VDIM];      // per-head V
__device__ float g_y   [(size_t)T_LEN * NH * VDIM];      // attention output, [t][h*128+d]

// -------------------- SGEMM: C[M,N] = A[M,K] * B[N,K]^T --------------------
// A row-major [M,K], B row-major [N,K] (both K-contiguous -> NT gemm).
// BM=BN=128, BK=8, 256 threads, 8x8 per-thread tile.
// Assumes: M % 128 == 0, K % 8 == 0, rows 16B-aligned. N may be ragged (guarded).
__global__ __launch_bounds__(256)
void sgemm_nt(const float* __restrict__ A, const float* __restrict__ B,
              float* __restrict__ C, int M, int N, int K)
{
    __shared__ float As[8][128];
    __shared__ float Bs[8][128];

    const int tid  = threadIdx.x;
    const int bm   = blockIdx.y * 128;
    const int bn   = blockIdx.x * 128;
    const int lrow = tid >> 1;          // 0..127
    const int lcol = (tid & 1) * 4;     // 0 or 4
    const int trow = (tid >> 4) * 8;    // 0..120
    const int tcol = (tid & 15) * 8;    // 0..120

    float acc[8][8];
#pragma unroll
    for (int i = 0; i < 8; i++)
#pragma unroll
        for (int j = 0; j < 8; j++) acc[i][j] = 0.f;

    const bool bvalid = (bn + lrow) < N;
    const float* Arow = A + (size_t)(bm + lrow) * K + lcol;
    const float* Brow = bvalid ? (B + (size_t)(bn + lrow) * K + lcol) : B;

    for (int k0 = 0; k0 < K; k0 += 8) {
        float4 a4 = *reinterpret_cast<const float4*>(Arow + k0);
        float4 b4 = make_float4(0.f, 0.f, 0.f, 0.f);
        if (bvalid) b4 = *reinterpret_cast<const float4*>(Brow + k0);
        As[lcol + 0][lrow] = a4.x; As[lcol + 1][lrow] = a4.y;
        As[lcol + 2][lrow] = a4.z; As[lcol + 3][lrow] = a4.w;
        Bs[lcol + 0][lrow] = b4.x; Bs[lcol + 1][lrow] = b4.y;
        Bs[lcol + 2][lrow] = b4.z; Bs[lcol + 3][lrow] = b4.w;
        __syncthreads();

#pragma unroll
        for (int kk = 0; kk < 8; kk++) {
            float4 a0 = *reinterpret_cast<const float4*>(&As[kk][trow]);
            float4 a1 = *reinterpret_cast<const float4*>(&As[kk][trow + 4]);
            float4 b0 = *reinterpret_cast<const float4*>(&Bs[kk][tcol]);
            float4 b1 = *reinterpret_cast<const float4*>(&Bs[kk][tcol + 4]);
            float ar[8] = {a0.x, a0.y, a0.z, a0.w, a1.x, a1.y, a1.z, a1.w};
            float br[8] = {b0.x, b0.y, b0.z, b0.w, b1.x, b1.y, b1.z, b1.w};
#pragma unroll
            for (int i = 0; i < 8; i++)
#pragma unroll
                for (int j = 0; j < 8; j++)
                    acc[i][j] = fmaf(ar[i], br[j], acc[i][j]);
        }
        __syncthreads();
    }

#pragma unroll
    for (int i = 0; i < 8; i++) {
        float* crow = C + (size_t)(bm + trow + i) * N;
#pragma unroll
        for (int j = 0; j < 8; j++) {
            int n = bn + tcol + j;
            if (n < N) crow[n] = acc[i][j];
        }
    }
}

// -------------------- RMSNorm in place on g_qa rows --------------------
__global__ __launch_bounds__(256)
void rmsnorm_qa(const float* __restrict__ w)
{
    __shared__ float red[256];
    __shared__ float s_inv;
    const int t = blockIdx.x;
    float* row = g_qa + (size_t)t * Q_LORA;
    float s = 0.f;
    for (int i = threadIdx.x; i < Q_LORA; i += 256) { float v = row[i]; s = fmaf(v, v, s); }
    red[threadIdx.x] = s; __syncthreads();
    for (int st = 128; st > 0; st >>= 1) {
        if (threadIdx.x < st) red[threadIdx.x] += red[threadIdx.x + st];
        __syncthreads();
    }
    if (threadIdx.x == 0) s_inv = rsqrtf(red[0] / (float)Q_LORA + EPS);
    __syncthreads();
    const float inv = s_inv;
    for (int i = threadIdx.x; i < Q_LORA; i += 256) row[i] = row[i] * inv * w[i];
}

// -------------------- kv prep: rmsnorm first 512 cols of g_kvf; rope k_pe --------------------
__global__ __launch_bounds__(256)
void kv_prep(const float* __restrict__ w, const float* __restrict__ freqs)
{
    __shared__ float red[256];
    __shared__ float s_inv;
    const int t = blockIdx.x;
    const float* row = g_kvf + (size_t)t * KVA_OUT;
    float s = 0.f;
    for (int i = threadIdx.x; i < KV_LORA; i += 256) { float v = row[i]; s = fmaf(v, v, s); }
    red[threadIdx.x] = s; __syncthreads();
    for (int st = 128; st > 0; st >>= 1) {
        if (threadIdx.x < st) red[threadIdx.x] += red[threadIdx.x + st];
        __syncthreads();
    }
    if (threadIdx.x == 0) s_inv = rsqrtf(red[0] / (float)KV_LORA + EPS);
    __syncthreads();
    const float inv = s_inv;
    for (int i = threadIdx.x; i < KV_LORA; i += 256)
        g_ckvn[(size_t)t * KV_LORA + i] = row[i] * inv * w[i];

    if (threadIdx.x < ROPE / 2) {
        int i = threadIdx.x;
        float x1 = row[KV_LORA + 2 * i];
        float x2 = row[KV_LORA + 2 * i + 1];
        float f = freqs[(size_t)t * (ROPE / 2) + i];
        float c = cosf(f), sn = sinf(f);
        g_kpe[(size_t)t * ROPE + 2 * i]     = x1 * c - x2 * sn;
        g_kpe[(size_t)t * ROPE + 2 * i + 1] = x1 * sn + x2 * c;
    }
}

// -------------------- assemble per-head qh/kh/v; rope q_pe --------------------
__global__ __launch_bounds__(256)
void assemble(const float* __restrict__ freqs)
{
    const int t = blockIdx.x;
    const int tid = threadIdx.x;

    // nope parts + V
    for (int idx = tid; idx < NH * NOPE; idx += 256) {
        int hh = idx >> 7, d = idx & 127;
        size_t base = ((size_t)hh * T_LEN + t) * QKD;
        g_qh[base + d] = g_q[(size_t)t * NH * QKD + hh * QKD + d];
        g_kh[base + d] = g_kv[(size_t)t * NH * 256 + hh * 256 + d];
        g_v[((size_t)hh * T_LEN + t) * VDIM + d] = g_kv[(size_t)t * NH * 256 + hh * 256 + 128 + d];
    }
    // rope parts
    for (int idx = tid; idx < NH * (ROPE / 2); idx += 256) {
        int hh = idx >> 5, i = idx & 31;
        float f = freqs[(size_t)t * (ROPE / 2) + i];
        float c = cosf(f), sn = sinf(f);
        const float* qp = g_q + (size_t)t * NH * QKD + hh * QKD + NOPE;
        float x1 = qp[2 * i], x2 = qp[2 * i + 1];
        size_t base = ((size_t)hh * T_LEN + t) * QKD + NOPE;
        g_qh[base + 2 * i]     = x1 * c - x2 * sn;
        g_qh[base + 2 * i + 1] = x1 * sn + x2 * c;
        g_kh[base + 2 * i]     = g_kpe[(size_t)t * ROPE + 2 * i];
        g_kh[base + 2 * i + 1] = g_kpe[(size_t)t * ROPE + 2 * i + 1];
    }
}

// -------------------- causal attention (online softmax), 1 warp = 1 query row --------------------
// grid: (T/8, H), 256 threads = 8 warps. 32-key K/V tiles in smem.
__global__ __launch_bounds__(256)
void mla_attn()
{
    __shared__ float Ks[32][QKD];
    __shared__ float Vs[32][VDIM];

    const int h = blockIdx.y;
    const int s0 = blockIdx.x * 8;
    const int tid = threadIdx.x;
    const int warp = tid >> 5, lane = tid & 31;
    const int s = s0 + warp;

    const float* Q = g_qh + ((size_t)h * T_LEN + s) * QKD;
    float qreg[6];
#pragma unroll
    for (int j = 0; j < 6; j++) qreg[j] = Q[lane * 6 + j];

    float m = -1e30f, l = 0.f;
    float o0 = 0.f, o1 = 0.f, o2 = 0.f, o3 = 0.f;

    const float* Kh = g_kh + (size_t)h * T_LEN * QKD;
    const float* Vh = g_v + (size_t)h * T_LEN * VDIM;
    const int smax = s0 + 7;

    for (int kb = 0; kb <= smax; kb += 32) {
        const float4* Ksrc = reinterpret_cast<const float4*>(Kh + (size_t)kb * QKD);
        float4* Kdst = reinterpret_cast<float4*>(&Ks[0][0]);
        for (int idx = tid; idx < 32 * QKD / 4; idx += 256) Kdst[idx] = Ksrc[idx];
        const float4* Vsrc = reinterpret_cast<const float4*>(Vh + (size_t)kb * VDIM);
        float4* Vdst = reinterpret_cast<float4*>(&Vs[0][0]);
        for (int idx = tid; idx < 32 * VDIM / 4; idx += 256) Vdst[idx] = Vsrc[idx];
        __syncthreads();

        const int nk = min(32, s - kb + 1);  // may be <=0 for leading warps on last tile
        for (int t = 0; t < nk; t++) {
            float d = qreg[0] * Ks[t][lane * 6 + 0];
            d = fmaf(qreg[1], Ks[t][lane * 6 + 1], d);
            d = fmaf(qreg[2], Ks[t][lane * 6 + 2], d);
            d = fmaf(qreg[3], Ks[t][lane * 6 + 3], d);
            d = fmaf(qreg[4], Ks[t][lane * 6 + 4], d);
            d = fmaf(qreg[5], Ks[t][lane * 6 + 5], d);
#pragma unroll
            for (int off = 16; off > 0; off >>= 1)
                d += __shfl_xor_sync(0xffffffffu, d, off);

            float logit = SOFTSCALE * d;
            float nm = fmaxf(m, logit);
            float sc = __expf(m - nm);
            float p  = __expf(logit - nm);
            l = l * sc + p;
            o0 = fmaf(p, Vs[t][lane * 4 + 0], o0 * sc);
            o1 = fmaf(p, Vs[t][lane * 4 + 1], o1 * sc);
            o2 = fmaf(p, Vs[t][lane * 4 + 2], o2 * sc);
            o3 = fmaf(p, Vs[t][lane * 4 + 3], o3 * sc);
            m = nm;
        }
        __syncthreads();
    }

    const float inv = 1.f / l;
    float* yo = g_y + (size_t)s * (NH * VDIM) + h * VDIM + lane * 4;
    yo[0] = o0 * inv; yo[1] = o1 * inv; yo[2] = o2 * inv; yo[3] = o3 * inv;
}

// GEMM launcher wrappers that take scratch via device symbols (avoids any
// host-side symbol-address API inside the captured region).
__global__ __launch_bounds__(1) void noop() {}

extern "C" void kernel_launch(void* const* d_in, const int* in_sizes, int n_in,
                              void* d_out, int out_size)
{
    const float* x        = (const float*)d_in[0];
    const float* freqs    = (const float*)d_in[1];
    // d_in[2] = mask (unused; we exploit causal structure directly)
    const float* wq_a     = (const float*)d_in[3];
    const float* q_norm_w = (const float*)d_in[4];
    const float* wq_b     = (const float*)d_in[5];
    const float* wkv_a    = (const float*)d_in[6];
    const float* kv_norm_w= (const float*)d_in[7];
    const float* wkv_b    = (const float*)d_in[8];
    const float* wo       = (const float*)d_in[9];
    float* out = (float*)d_out;

    static float *qa = nullptr, *q, *kvf, *ckvn, *qh_p, *y;
    // cudaGetSymbolAddress is not a stream op; calling it each time is
    // deterministic and capture-safe. (No caching semantics depend on it.)
    cudaGetSymbolAddress((void**)&qa,   g_qa);
    cudaGetSymbolAddress((void**)&q,    g_q);
    cudaGetSymbolAddress((void**)&kvf,  g_kvf);
    cudaGetSymbolAddress((void**)&ckvn, g_ckvn);
    cudaGetSymbolAddress((void**)&qh_p, g_qh);
    cudaGetSymbolAddress((void**)&y,    g_y);
    float* kv_p; cudaGetSymbolAddress((void**)&kv_p, g_kv);

    dim3 blk(256);
    const int MB = T_LEN / 128;

    // q_a = x @ wq_a^T ; rmsnorm
    sgemm_nt<<<dim3(Q_LORA / 128, MB), blk>>>(x, wq_a, qa, T_LEN, Q_LORA, DIMX);
    rmsnorm_qa<<<T_LEN, blk>>>(q_norm_w);
    // q = qa @ wq_b^T
    sgemm_nt<<<dim3(NH * QKD / 128, MB), blk>>>(qa, wq_b, q, T_LEN, NH * QKD, Q_LORA);
    // kvf = x @ wkv_a^T
    sgemm_nt<<<dim3((KVA_OUT + 127) / 128, MB), blk>>>(x, wkv_a, kvf, T_LEN, KVA_OUT, DIMX);
    // rmsnorm(c_kv) + rope(k_pe)
    kv_prep<<<T_LEN, blk>>>(kv_norm_w, freqs);
    // kv = ckvn @ wkv_b^T
    sgemm_nt<<<dim3(NH * 256 / 128, MB), blk>>>(ckvn, wkv_b, kv_p, T_LEN, NH * 256, KV_LORA);
    // build qh/kh/v (rope q_pe, broadcast k_pe)
    assemble<<<T_LEN, blk>>>(freqs);
    // causal attention
    mla_attn<<<dim3(T_LEN / 8, NH), blk>>>();
    // out = y @ wo^T
    sgemm_nt<<<dim3(DIMX / 128, MB), blk>>>(y, wo, out, T_LEN, DIMX, NH * VDIM);
}

// round 3
// speedup vs baseline: 1.5272x; 1.5272x over previous
#include <cuda_runtime.h>
#include <math.h>

// Problem constants
#define T_LEN 2048
#define DIMX 2048
#define NH 16
#define NOPE 128
#define ROPE 64
#define VDIM 128
#define QKD 192          // NOPE + ROPE
#define Q_LORA 768
#define KV_LORA 512
#define KVA_OUT 576      // KV_LORA + ROPE
#define SOFTSCALE (-96.0f)   // QKD * -0.5 in the reference (multiplication!)
#define EPS 1e-6f

// -------------------- scratch (device globals; no allocs allowed) --------------------
__device__ float g_qa  [(size_t)T_LEN * Q_LORA];
__device__ float g_q   [(size_t)T_LEN * NH * QKD];
__device__ float g_kvf [(size_t)T_LEN * KVA_OUT];
__device__ float g_ckvn[(size_t)T_LEN * KV_LORA];
__device__ float g_kpe [(size_t)T_LEN * ROPE];
__device__ float g_kv  [(size_t)T_LEN * NH * (NOPE + VDIM)];
__device__ float g_qh  [(size_t)NH * T_LEN * QKD];
__device__ float g_kh  [(size_t)NH * T_LEN * QKD];
__device__ float g_v   [(size_t)NH * T_LEN * VDIM];
__device__ float g_y   [(size_t)T_LEN * NH * VDIM];

// -------------------- SGEMM v2: C[M,N] = A[M,K] * B[N,K]^T --------------------
// 64x128 tile, BK=16, 256 threads, 4x8 per thread, register-prefetch pipeline.
// M%64==0, K%16==0, N%64==0 (ragged last 64-col half handled).
#define ASW 68
#define BSW 132
__global__ __launch_bounds__(256)
void sgemm2(const float* __restrict__ A, const float* __restrict__ B,
            float* __restrict__ C, int M, int N, int K)
{
    __shared__ float As[16 * ASW];
    __shared__ float Bs[16 * BSW];

    const int tid = threadIdx.x;
    const int bm = blockIdx.y * 64;
    const int bn = blockIdx.x * 128;
    const int tx = tid & 15;          // 16 col groups of (4 + 4 @ +64)
    const int ty = tid >> 4;          // 16 row groups of 4

    const int lr = tid >> 2;          // 0..63  (load row)
    const int lk = (tid & 3) * 4;     // 0,4,8,12 (load k)

    const float* Ap = A + (size_t)(bm + lr) * K + lk;
    const int bn0 = bn + lr, bn1 = bn + 64 + lr;
    const bool v0 = bn0 < N, v1 = bn1 < N;
    const float* Bp0 = B + (size_t)(v0 ? bn0 : 0) * K + lk;
    const float* Bp1 = B + (size_t)(v1 ? bn1 : 0) * K + lk;

    float acc[4][8];
#pragma unroll
    for (int i = 0; i < 4; i++)
#pragma unroll
        for (int j = 0; j < 8; j++) acc[i][j] = 0.f;

    float4 pa  = *(const float4*)Ap;
    float4 pb0 = v0 ? *(const float4*)Bp0 : make_float4(0.f, 0.f, 0.f, 0.f);
    float4 pb1 = v1 ? *(const float4*)Bp1 : make_float4(0.f, 0.f, 0.f, 0.f);

    for (int k0 = 0; k0 < K; k0 += 16) {
        As[(lk + 0) * ASW + lr] = pa.x;
        As[(lk + 1) * ASW + lr] = pa.y;
        As[(lk + 2) * ASW + lr] = pa.z;
        As[(lk + 3) * ASW + lr] = pa.w;
        Bs[(lk + 0) * BSW + lr] = pb0.x;
        Bs[(lk + 1) * BSW + lr] = pb0.y;
        Bs[(lk + 2) * BSW + lr] = pb0.z;
        Bs[(lk + 3) * BSW + lr] = pb0.w;
        Bs[(lk + 0) * BSW + 64 + lr] = pb1.x;
        Bs[(lk + 1) * BSW + 64 + lr] = pb1.y;
        Bs[(lk + 2) * BSW + 64 + lr] = pb1.z;
        Bs[(lk + 3) * BSW + 64 + lr] = pb1.w;
        __syncthreads();

        if (k0 + 16 < K) {
            pa = *(const float4*)(Ap + k0 + 16);
            if (v0) pb0 = *(const float4*)(Bp0 + k0 + 16);
            if (v1) pb1 = *(const float4*)(Bp1 + k0 + 16);
        }

#pragma unroll
        for (int kk = 0; kk < 16; kk++) {
            float4 a  = *(const float4*)&As[kk * ASW + ty * 4];
            float4 b0 = *(const float4*)&Bs[kk * BSW + tx * 4];
            float4 b1 = *(const float4*)&Bs[kk * BSW + 64 + tx * 4];
            float ar[4] = {a.x, a.y, a.z, a.w};
            float br[8] = {b0.x, b0.y, b0.z, b0.w, b1.x, b1.y, b1.z, b1.w};
#pragma unroll
            for (int i = 0; i < 4; i++)
#pragma unroll
                for (int j = 0; j < 8; j++)
                    acc[i][j] = fmaf(ar[i], br[j], acc[i][j]);
        }
        __syncthreads();
    }

    const bool h0 = (bn + 64) <= N;
    const bool h1 = (bn + 128) <= N;
#pragma unroll
    for (int i = 0; i < 4; i++) {
        float* crow = C + (size_t)(bm + ty * 4 + i) * N;
        if (h0) *(float4*)(crow + bn + tx * 4) =
            make_float4(acc[i][0], acc[i][1], acc[i][2], acc[i][3]);
        if (h1) *(float4*)(crow + bn + 64 + tx * 4) =
            make_float4(acc[i][4], acc[i][5], acc[i][6], acc[i][7]);
    }
}

// -------------------- RMSNorm in place on g_qa rows --------------------
__global__ __launch_bounds__(256)
void rmsnorm_qa(const float* __restrict__ w)
{
    __shared__ float red[256];
    __shared__ float s_inv;
    const int t = blockIdx.x;
    float* row = g_qa + (size_t)t * Q_LORA;
    float s = 0.f;
    for (int i = threadIdx.x; i < Q_LORA; i += 256) { float v = row[i]; s = fmaf(v, v, s); }
    red[threadIdx.x] = s; __syncthreads();
    for (int st = 128; st > 0; st >>= 1) {
        if (threadIdx.x < st) red[threadIdx.x] += red[threadIdx.x + st];
        __syncthreads();
    }
    if (threadIdx.x == 0) s_inv = rsqrtf(red[0] / (float)Q_LORA + EPS);
    __syncthreads();
    const float inv = s_inv;
    for (int i = threadIdx.x; i < Q_LORA; i += 256) row[i] = row[i] * inv * w[i];
}

// -------------------- kv prep: rmsnorm first 512 cols of g_kvf; rope k_pe --------------------
__global__ __launch_bounds__(256)
void kv_prep(const float* __restrict__ w, const float* __restrict__ freqs)
{
    __shared__ float red[256];
    __shared__ float s_inv;
    const int t = blockIdx.x;
    const float* row = g_kvf + (size_t)t * KVA_OUT;
    float s = 0.f;
    for (int i = threadIdx.x; i < KV_LORA; i += 256) { float v = row[i]; s = fmaf(v, v, s); }
    red[threadIdx.x] = s; __syncthreads();
    for (int st = 128; st > 0; st >>= 1) {
        if (threadIdx.x < st) red[threadIdx.x] += red[threadIdx.x + st];
        __syncthreads();
    }
    if (threadIdx.x == 0) s_inv = rsqrtf(red[0] / (float)KV_LORA + EPS);
    __syncthreads();
    const float inv = s_inv;
    for (int i = threadIdx.x; i < KV_LORA; i += 256)
        g_ckvn[(size_t)t * KV_LORA + i] = row[i] * inv * w[i];

    if (threadIdx.x < ROPE / 2) {
        int i = threadIdx.x;
        float x1 = row[KV_LORA + 2 * i];
        float x2 = row[KV_LORA + 2 * i + 1];
        float f = freqs[(size_t)t * (ROPE / 2) + i];
        float c = cosf(f), sn = sinf(f);
        g_kpe[(size_t)t * ROPE + 2 * i]     = x1 * c - x2 * sn;
        g_kpe[(size_t)t * ROPE + 2 * i + 1] = x1 * sn + x2 * c;
    }
}

// -------------------- assemble per-head qh/kh/v; rope q_pe --------------------
__global__ __launch_bounds__(256)
void assemble(const float* __restrict__ freqs)
{
    const int t = blockIdx.x;
    const int tid = threadIdx.x;

    for (int idx = tid; idx < NH * NOPE; idx += 256) {
        int hh = idx >> 7, d = idx & 127;
        size_t base = ((size_t)hh * T_LEN + t) * QKD;
        g_qh[base + d] = g_q[(size_t)t * NH * QKD + hh * QKD + d];
        g_kh[base + d] = g_kv[(size_t)t * NH * 256 + hh * 256 + d];
        g_v[((size_t)hh * T_LEN + t) * VDIM + d] = g_kv[(size_t)t * NH * 256 + hh * 256 + 128 + d];
    }
    for (int idx = tid; idx < NH * (ROPE / 2); idx += 256) {
        int hh = idx >> 5, i = idx & 31;
        float f = freqs[(size_t)t * (ROPE / 2) + i];
        float c = cosf(f), sn = sinf(f);
        const float* qp = g_q + (size_t)t * NH * QKD + hh * QKD + NOPE;
        float x1 = qp[2 * i], x2 = qp[2 * i + 1];
        size_t base = ((size_t)hh * T_LEN + t) * QKD + NOPE;
        g_qh[base + 2 * i]     = x1 * c - x2 * sn;
        g_qh[base + 2 * i + 1] = x1 * sn + x2 * c;
        g_kh[base + 2 * i]     = g_kpe[(size_t)t * ROPE + 2 * i];
        g_kh[base + 2 * i + 1] = g_kpe[(size_t)t * ROPE + 2 * i + 1];
    }
}

// -------------------- attention v2: lane-per-key, 4 queries per warp --------------------
// Block: 256 threads = 8 warps x 4 queries = 32 queries; 32-key tiles.
// Dynamic smem: Qs[32][192] | Ks[32][193] | Vs[32][128]
#define KSW 193
__global__ __launch_bounds__(256)
void mla_attn2()
{
    extern __shared__ float sm[];
    float* Qs = sm;                       // 32*192
    float* Ks = sm + 32 * QKD;            // 32*193
    float* Vs = Ks + 32 * KSW;            // 32*128

    const int h = blockIdx.y;
    const int qb = blockIdx.x * 32;
    const int tid = threadIdx.x;
    const int warp = tid >> 5, lane = tid & 31;

    const float* Qg = g_qh + ((size_t)h * T_LEN + qb) * QKD;
    for (int idx = tid; idx < 32 * QKD / 4; idx += 256)
        ((float4*)Qs)[idx] = ((const float4*)Qg)[idx];

    float m[4], l[4], o[4][4];
#pragma unroll
    for (int j = 0; j < 4; j++) {
        m[j] = -1e30f; l[j] = 0.f;
        o[j][0] = o[j][1] = o[j][2] = o[j][3] = 0.f;
    }

    const float* Kh = g_kh + (size_t)h * T_LEN * QKD;
    const float* Vh = g_v  + (size_t)h * T_LEN * VDIM;
    const int q0i = qb + warp * 4;

    for (int kb = 0; kb <= qb + 31; kb += 32) {
        __syncthreads();
        for (int idx = tid; idx < 32 * 48; idx += 256) {
            int key = idx / 48, d4 = idx % 48;
            float4 v = ((const float4*)(Kh + (size_t)(kb + key) * QKD))[d4];
            float* dst = Ks + key * KSW + d4 * 4;
            dst[0] = v.x; dst[1] = v.y; dst[2] = v.z; dst[3] = v.w;
        }
        for (int idx = tid; idx < 32 * 32; idx += 256)
            ((float4*)Vs)[idx] = ((const float4*)(Vh + (size_t)kb * VDIM))[idx];
        __syncthreads();

        // --- logits: lane's key vs warp's 4 queries ---
        const float* krow = Ks + lane * KSW;
        const float4* q40 = (const float4*)(Qs + (warp * 4 + 0) * QKD);
        const float4* q41 = (const float4*)(Qs + (warp * 4 + 1) * QKD);
        const float4* q42 = (const float4*)(Qs + (warp * 4 + 2) * QKD);
        const float4* q43 = (const float4*)(Qs + (warp * 4 + 3) * QKD);
        float acc[4] = {0.f, 0.f, 0.f, 0.f};
#pragma unroll 8
        for (int d4 = 0; d4 < 48; d4++) {
            float k0v = krow[d4 * 4 + 0];
            float k1v = krow[d4 * 4 + 1];
            float k2v = krow[d4 * 4 + 2];
            float k3v = krow[d4 * 4 + 3];
            float4 a;
            a = q40[d4]; acc[0] = fmaf(a.x,k0v,fmaf(a.y,k1v,fmaf(a.z,k2v,fmaf(a.w,k3v,acc[0]))));
            a = q41[d4]; acc[1] = fmaf(a.x,k0v,fmaf(a.y,k1v,fmaf(a.z,k2v,fmaf(a.w,k3v,acc[1]))));
            a = q42[d4]; acc[2] = fmaf(a.x,k0v,fmaf(a.y,k1v,fmaf(a.z,k2v,fmaf(a.w,k3v,acc[2]))));
            a = q43[d4]; acc[3] = fmaf(a.x,k0v,fmaf(a.y,k1v,fmaf(a.z,k2v,fmaf(a.w,k3v,acc[3]))));
        }

        // --- online softmax update (4 queries in parallel across lanes) ---
        const int key = kb + lane;
        float p[4];
#pragma unroll
        for (int j = 0; j < 4; j++) {
            float logit = (key <= q0i + j) ? SOFTSCALE * acc[j] : -INFINITY;
            float tmax = logit;
#pragma unroll
            for (int off = 16; off; off >>= 1)
                tmax = fmaxf(tmax, __shfl_xor_sync(0xffffffffu, tmax, off));
            float nm = fmaxf(m[j], tmax);
            float sc = __expf(m[j] - nm);
            p[j] = __expf(logit - nm);
            float ts = p[j];
#pragma unroll
            for (int off = 16; off; off >>= 1)
                ts += __shfl_xor_sync(0xffffffffu, ts, off);
            l[j] = l[j] * sc + ts;
            m[j] = nm;
            o[j][0] *= sc; o[j][1] *= sc; o[j][2] *= sc; o[j][3] *= sc;
        }

        // --- PV: lane owns 4 output dims (lane*4..+3) ---
#pragma unroll 4
        for (int k = 0; k < 32; k++) {
            float4 vv = ((const float4*)(Vs + k * VDIM))[lane];
#pragma unroll
            for (int j = 0; j < 4; j++) {
                float pk = __shfl_sync(0xffffffffu, p[j], k);
                o[j][0] = fmaf(pk, vv.x, o[j][0]);
                o[j][1] = fmaf(pk, vv.y, o[j][1]);
                o[j][2] = fmaf(pk, vv.z, o[j][2]);
                o[j][3] = fmaf(pk, vv.w, o[j][3]);
            }
        }
    }

#pragma unroll
    for (int j = 0; j < 4; j++) {
        float inv = 1.f / l[j];
        float4 r = make_float4(o[j][0]*inv, o[j][1]*inv, o[j][2]*inv, o[j][3]*inv);
        *(float4*)(g_y + (size_t)(q0i + j) * (NH * VDIM) + h * VDIM + lane * 4) = r;
    }
}

#define ATTN_SMEM ((32 * QKD + 32 * KSW + 32 * VDIM) * 4)

extern "C" void kernel_launch(void* const* d_in, const int* in_sizes, int n_in,
                              void* d_out, int out_size)
{
    const float* x        = (const float*)d_in[0];
    const float* freqs    = (const float*)d_in[1];
    // d_in[2] = mask (unused; causal structure exploited directly)
    const float* wq_a     = (const float*)d_in[3];
    const float* q_norm_w = (const float*)d_in[4];
    const float* wq_b     = (const float*)d_in[5];
    const float* wkv_a    = (const float*)d_in[6];
    const float* kv_norm_w= (const float*)d_in[7];
    const float* wkv_b    = (const float*)d_in[8];
    const float* wo       = (const float*)d_in[9];
    float* out = (float*)d_out;

    float *qa, *q, *kvf, *ckvn, *kv_p, *y;
    cudaGetSymbolAddress((void**)&qa,   g_qa);
    cudaGetSymbolAddress((void**)&q,    g_q);
    cudaGetSymbolAddress((void**)&kvf,  g_kvf);
    cudaGetSymbolAddress((void**)&ckvn, g_ckvn);
    cudaGetSymbolAddress((void**)&kv_p, g_kv);
    cudaGetSymbolAddress((void**)&y,    g_y);

    cudaFuncSetAttribute(mla_attn2, cudaFuncAttributeMaxDynamicSharedMemorySize, ATTN_SMEM);

    dim3 blk(256);
    const int MB = T_LEN / 64;   // 32 row-blocks

    // q_a = x @ wq_a^T ; rmsnorm
    sgemm2<<<dim3(Q_LORA / 128, MB), blk>>>(x, wq_a, qa, T_LEN, Q_LORA, DIMX);
    rmsnorm_qa<<<T_LEN, blk>>>(q_norm_w);
    // q = qa @ wq_b^T
    sgemm2<<<dim3(NH * QKD / 128, MB), blk>>>(qa, wq_b, q, T_LEN, NH * QKD, Q_LORA);
    // kvf = x @ wkv_a^T   (N=576 ragged)
    sgemm2<<<dim3((KVA_OUT + 127) / 128, MB), blk>>>(x, wkv_a, kvf, T_LEN, KVA_OUT, DIMX);
    // rmsnorm(c_kv) + rope(k_pe)
    kv_prep<<<T_LEN, blk>>>(kv_norm_w, freqs);
    // kv = ckvn @ wkv_b^T
    sgemm2<<<dim3(NH * 256 / 128, MB), blk>>>(ckvn, wkv_b, kv_p, T_LEN, NH * 256, KV_LORA);
    // build qh/kh/v
    assemble<<<T_LEN, blk>>>(freqs);
    // causal attention
    mla_attn2<<<dim3(T_LEN / 32, NH), blk, ATTN_SMEM>>>();
    // out = y @ wo^T
    sgemm2<<<dim3(DIMX / 128, MB), blk>>>(y, wo, out, T_LEN, DIMX, NH * VDIM);
}